// round 14
// baseline (speedup 1.0000x reference)
#include <cuda_runtime.h>
#include <cuda_fp16.h>

#define BATCH 512
#define TLEN  256
#define HID   512
#define HALF  256
#define TGT   28

#define NTHREADS 256
#define NCTAS 128
#define GSZ (NCTAS * NTHREADS)
#define WSMEM_BYTES 65536   // 32 kt x 4 j2 x 512B (paired-n8 fp16 W fragments)

// ---------------- device scratch ----------------
// A(h) fragment per (m16,k16): 512B = lane*16 (4 .f16x2 regs)
__device__ __align__(16) unsigned char g_hfrag[2][1 << 19];
// B(W) fragment per (n8,k16): 256B = lane*8 : {b0, b1} fp16x2
__device__ __align__(16) unsigned char g_Wfrag[2 << 20];
__device__ __align__(16) float g_hfin[BATCH * HID];
__device__ unsigned int g_barcnt0;
__device__ volatile unsigned int g_bargen0;
__device__ unsigned int g_flag[4 * 32];       // per (group, producer tileN)

// full-grid barrier (sense-reversing; replay-safe)
__device__ __forceinline__ void gridbar0() {
    __threadfence();
    __syncthreads();
    if (threadIdx.x == 0) {
        unsigned int gen = g_bargen0;
        if (atomicAdd(&g_barcnt0, 1u) == NCTAS - 1u) {
            g_barcnt0 = 0u;
            __threadfence();
            g_bargen0 = gen + 1u;
        } else {
            while (g_bargen0 == gen) { }
            __threadfence();
        }
    }
    __syncthreads();
}

// 32-CTA group barrier (R12-proven pattern, 32 flags)
__device__ __forceinline__ void groupbar(unsigned int* F, int tileN, unsigned int ep,
                                         int wti, int lane) {
    __threadfence();               // release: each thread's STGs visible (gpu scope)
    __syncthreads();
    if (wti == 0) {
        if (lane == 0)
            *(volatile unsigned int*)&F[tileN] = ep;
        volatile unsigned int* fp = &F[lane];
        while (__any_sync(0xffffffffu, *fp < ep)) { }
        if (lane == 0)
            __threadfence();       // acquire + CCTL.IVALL (L1 safe for plain LDG)
    }
    __syncthreads();
}

__device__ __forceinline__ float sigf(float x)  { return 1.0f / (1.0f + __expf(-x)); }
__device__ __forceinline__ float tanhft(float x){ return 1.0f - 2.0f / (__expf(2.0f * x) + 1.0f); }

__device__ __forceinline__ unsigned int packh(float a, float b) {
    __half2 h = __floats2half2_rn(a, b);
    return reinterpret_cast<unsigned int&>(h);
}

#define MMA_F16(c, A, B0, B1)                                               \
    asm volatile("mma.sync.aligned.m16n8k16.row.col.f32.f16.f16.f32 "       \
                 "{%0,%1,%2,%3}, {%4,%5,%6,%7}, {%8,%9}, {%0,%1,%2,%3};"    \
                 : "+f"(c[0]), "+f"(c[1]), "+f"(c[2]), "+f"(c[3])           \
                 : "r"(A.x), "r"(A.y), "r"(A.z), "r"(A.w), "r"(B0), "r"(B1))

__global__ __launch_bounds__(NTHREADS, 1)
void lstm_mma_kernel(
    const float* __restrict__ seq,  const float* __restrict__ W_ih,
    const float* __restrict__ W_hh, const float* __restrict__ b_ih,
    const float* __restrict__ b_hh, const float* __restrict__ fc1w,
    const float* __restrict__ fc1b, const float* __restrict__ fc2w,
    const float* __restrict__ fc2b, float* __restrict__ out)
{
    extern __shared__ unsigned char wsm[];                 // 64KB W fragments
    __shared__ __align__(16) float stage[8][16][18];       // per-warp h tile (fp32)
    __shared__ __align__(16) float4 sm_wih[16], sm_bias[16];
    __shared__ __align__(16) float hs[4][HID];             // fc1 input rows
    __shared__ __align__(16) float sm_hid[4][HALF];        // fc1 output rows

    const int tid  = threadIdx.x;
    const int cta  = blockIdx.x;
    const int gid  = cta * NTHREADS + tid;
    const int lane = tid & 31;
    const int wti  = tid >> 5;
    const int gq   = lane >> 2;
    const int tg   = lane & 3;

    // ---- prep: W fp16 fragments (gate-interleave reorder). col n:
    // w16=n&15, gate=((w16>>3)<<1)|(w16&1), unit=(n>>4)*4+((w16&7)>>1)
    for (int it = gid; it < 256 * 32 * 32; it += GSZ) {
        int ln  = it & 31;
        int k16 = (it >> 5) & 31;
        int n8  = it >> 10;
        int n   = n8 * 8 + (ln >> 2);
        int w16 = n & 15;
        int gate = ((w16 >> 3) << 1) | (w16 & 1);
        int unit = (n >> 4) * 4 + ((w16 & 7) >> 1);
        const float* wr = W_hh + (gate * HID + unit) * HID + k16 * 16 + ((ln & 3) << 1);
        float2 p0 = *(const float2*)wr;          // k, k+1
        float2 p1 = *(const float2*)(wr + 8);    // k+8, k+9
        uint2 v;
        v.x = packh(p0.x, p0.y);
        v.y = packh(p1.x, p1.y);
        *(uint2*)(g_Wfrag + (((n8 << 5) + k16) << 8) + ln * 8) = v;
    }
    {   // zero h fragments buffer 0 (h = 0)
        uint4 z = make_uint4(0, 0, 0, 0);
        uint4* hz = (uint4*)g_hfrag[0];
        for (int e = gid; e < (1 << 15); e += GSZ) hz[e] = z;
    }
    gridbar0();

    // ---- per-CTA geometry: tile = 128 batch rows x 64 gate cols ----
    const int tileM = cta & 3;             // group 0..3
    const int tileN = cta >> 2;            // 0..31 (64 gate-cols = 16 units)
    const int m16g  = tileM * 8 + wti;

    // copy this CTA's W fragments to smem, paired-n8 layout:
    // chunk (kt*4 + j2) of 512B; lane slot 16B = {frag(2j2)[lane] 8B, frag(2j2+1)[lane] 8B}
    {
        uint4* s4 = (uint4*)wsm;
        for (int e = tid; e < WSMEM_BYTES / 16; e += NTHREADS) {
            int w = e & 31, c = e >> 5;
            int kt = c >> 2, j2 = c & 3;
            const unsigned char* f0 =
                g_Wfrag + ((((tileN * 8 + 2 * j2)     << 5) + kt) << 8) + w * 8;
            const unsigned char* f1 =
                g_Wfrag + ((((tileN * 8 + 2 * j2 + 1) << 5) + kt) << 8) + w * 8;
            uint2 lo = __ldcg((const uint2*)f0);
            uint2 hi = __ldcg((const uint2*)f1);
            s4[e] = make_uint4(lo.x, lo.y, hi.x, hi.y);
        }
    }
    for (int e = tid; e < 64; e += NTHREADS) {
        int u = e >> 2, g = e & 3;
        int ku = tileN * 16 + u;
        ((float*)sm_wih)[e]  = W_ih[g * HID + ku];
        ((float*)sm_bias)[e] = b_ih[g * HID + ku] + b_hh[g * HID + ku];
    }
    __syncthreads();

    float creg[2][4];                      // [rh][unit-quad b]
    #pragma unroll
    for (int r = 0; r < 2; ++r)
        #pragma unroll
        for (int b = 0; b < 4; ++b) creg[r][b] = 0.0f;

    const int row_base = tileM * 128 + wti * 16 + gq;
    const int c0 = tileN;                  // rotated k-loop start
    unsigned int* F = g_flag + tileM * 32;

    // ---- recurrent loop ----
    for (int t = 0; t < TLEN; ++t) {
        const unsigned char* hin  = g_hfrag[t & 1];
        unsigned char*       hout = g_hfrag[(t + 1) & 1];
        const unsigned char* abase = hin + ((size_t)(m16g * 32) << 9) + lane * 16;
        const unsigned char* wbase = wsm + lane * 16;

        // prefetch xv early (L1-cold after IVALL)
        float xv0 = seq[row_base * TLEN + t];
        float xv1 = seq[(row_base + 8) * TLEN + t];

        float acc[8][4];
        #pragma unroll
        for (int j = 0; j < 8; ++j)
            #pragma unroll
            for (int c = 0; c < 4; ++c) acc[j][c] = 0.0f;

        uint4 ah[4];                       // depth-4 A prefetch (plain LDG -> L1)
        #pragma unroll
        for (int p = 0; p < 4; ++p)
            ah[p] = *(const uint4*)(abase + ((size_t)((c0 + p) & 31) << 9));

        #pragma unroll 4
        for (int kt = 0; kt < 32; ++kt) {
            const int s = kt & 3;
            const int c = (c0 + kt) & 31;
            uint4 b4[4];
            #pragma unroll
            for (int j2 = 0; j2 < 4; ++j2)
                b4[j2] = *(const uint4*)(wbase + (((c << 2) + j2) << 9));
            #pragma unroll
            for (int j2 = 0; j2 < 4; ++j2) {
                MMA_F16(acc[2*j2    ], ah[s], b4[j2].x, b4[j2].y);
                MMA_F16(acc[2*j2 + 1], ah[s], b4[j2].z, b4[j2].w);
            }
            if (kt + 4 < 32)
                ah[s] = *(const uint4*)(abase + ((size_t)((c0 + kt + 4) & 31) << 9));
        }

        // ---- epilogue: gates -> c,h ; stage h (fp32) ----
        #pragma unroll
        for (int rh = 0; rh < 2; ++rh) {
            float xv = rh ? xv1 : xv0;
            #pragma unroll
            for (int b = 0; b < 4; ++b) {
                float4 wv = sm_wih[b * 4 + tg];
                float4 bv = sm_bias[b * 4 + tg];
                float gi = acc[2*b  ][rh*2+0] + xv * wv.x + bv.x;
                float gf = acc[2*b  ][rh*2+1] + xv * wv.y + bv.y;
                float gg = acc[2*b+1][rh*2+0] + xv * wv.z + bv.z;
                float go = acc[2*b+1][rh*2+1] + xv * wv.w + bv.w;
                float cc = sigf(gf) * creg[rh][b] + sigf(gi) * tanhft(gg);
                creg[rh][b] = cc;
                float hv = sigf(go) * tanhft(cc);
                stage[wti][gq + rh * 8][b * 4 + tg] = hv;
                if (t == TLEN - 1)
                    g_hfin[(row_base + rh * 8) * HID + tileN * 16 + b * 4 + tg] = hv;
            }
        }
        __syncwarp();
        // repack: warp writes the COMPLETE A fragment (m16g, k16 = tileN)
        {
            const float* st0 = &stage[wti][gq][0];
            const float* st1 = &stage[wti][gq + 8][0];
            uint4 v;
            v.x = packh(st0[2*tg],     st0[2*tg + 1]);
            v.y = packh(st1[2*tg],     st1[2*tg + 1]);
            v.z = packh(st0[8 + 2*tg], st0[8 + 2*tg + 1]);
            v.w = packh(st1[8 + 2*tg], st1[8 + 2*tg + 1]);
            *(uint4*)(hout + ((size_t)(m16g * 32 + tileN) << 9) + lane * 16) = v;
        }

        groupbar(F, tileN, (unsigned int)(t + 1), wti, lane);
    }

    // ---- full sync; reset flags for next graph replay ----
    gridbar0();
    if (tid == 0)
        *(volatile unsigned int*)&g_flag[tileM * 32 + tileN] = 0u;

    // ---- fc1: hid = relu(h @ fc1w^T + fc1b), 4 batch rows per CTA ----
    const int bb = cta * 4;
    {
        for (int e = tid; e < 4 * HID; e += NTHREADS)
            hs[e >> 9][e & 511] = g_hfin[(bb + (e >> 9)) * HID + (e & 511)];
        __syncthreads();
        int n = tid;                            // HALF == 256 == NTHREADS
        const float* wr = fc1w + n * HID;
        float s0 = fc1b[n], s1 = s0, s2 = s0, s3 = s0;
        #pragma unroll 8
        for (int k = 0; k < HID; ++k) {
            float w = wr[k];
            s0 += hs[0][k] * w; s1 += hs[1][k] * w;
            s2 += hs[2][k] * w; s3 += hs[3][k] * w;
        }
        sm_hid[0][n] = fmaxf(s0, 0.0f);
        sm_hid[1][n] = fmaxf(s1, 0.0f);
        sm_hid[2][n] = fmaxf(s2, 0.0f);
        sm_hid[3][n] = fmaxf(s3, 0.0f);
    }
    __syncthreads();

    // ---- fc2 (rows bb..bb+3) ----
    for (int i = tid; i < 4 * TGT; i += NTHREADS) {
        int r  = i / TGT;
        int tt = i - r * TGT;
        const float* hr = sm_hid[r];
        const float* wr = fc2w + tt * HALF;
        float s = fc2b[tt];
        #pragma unroll 8
        for (int k = 0; k < HALF; ++k) s += hr[k] * wr[k];
        out[(bb + r) * TGT + tt] = s;
    }
}

extern "C" void kernel_launch(void* const* d_in, const int* in_sizes, int n_in,
                              void* d_out, int out_size) {
    (void)in_sizes; (void)n_in; (void)out_size;
    cudaFuncSetAttribute(lstm_mma_kernel,
                         cudaFuncAttributeMaxDynamicSharedMemorySize, WSMEM_BYTES);
    lstm_mma_kernel<<<NCTAS, NTHREADS, WSMEM_BYTES>>>(
        (const float*)d_in[0], (const float*)d_in[1], (const float*)d_in[2],
        (const float*)d_in[3], (const float*)d_in[4], (const float*)d_in[5],
        (const float*)d_in[6], (const float*)d_in[7], (const float*)d_in[8],
        (float*)d_out);
}

// round 15
// speedup vs baseline: 1.7559x; 1.7559x over previous
#include <cuda_runtime.h>
#include <cuda_fp16.h>

#define BATCH 512
#define TLEN  256
#define HID   512
#define HALF  256
#define TGT   28

#define NTHREADS 256
#define NCTAS 256
#define GSZ (NCTAS * NTHREADS)
#define WSMEM_BYTES 32768   // 32 k16 x 4 n8 x 256B (fp16 W fragments)

// ---------------- device scratch ----------------
// A(h) fragment per (m16,k16): 512B = lane*16 (4 .f16x2 regs)
__device__ __align__(16) unsigned char g_hfrag[2][1 << 19];
// B(W) fragment per (n8,k16): 256B = lane*8 : {b0, b1} fp16x2
__device__ __align__(16) unsigned char g_Wfrag[2 << 20];
__device__ __align__(16) float g_hfin[BATCH * HID];
__device__ unsigned int g_barcnt0;
__device__ volatile unsigned int g_bargen0;
// arrival counters, one per (group, producer CTA), 128B apart (L2-atom friendly)
__device__ unsigned int g_cnt[4][64][32];

// full-grid barrier (sense-reversing; replay-safe; prep/tail only)
__device__ __forceinline__ void gridbar0() {
    __threadfence();
    __syncthreads();
    if (threadIdx.x == 0) {
        unsigned int gen = g_bargen0;
        if (atomicAdd(&g_barcnt0, 1u) == NCTAS - 1u) {
            g_barcnt0 = 0u;
            __threadfence();
            g_bargen0 = gen + 1u;
        } else {
            while (g_bargen0 == gen) { }
            __threadfence();
        }
    }
    __syncthreads();
}

__device__ __forceinline__ unsigned int ld_acquire(const unsigned int* p) {
    unsigned int v;
    asm volatile("ld.acquire.gpu.global.b32 %0, [%1];" : "=r"(v) : "l"(p) : "memory");
    return v;
}
__device__ __forceinline__ void red_release_add1(unsigned int* p) {
    asm volatile("red.release.gpu.global.add.u32 [%0], %1;" :: "l"(p), "r"(1u) : "memory");
}

__device__ __forceinline__ float sigf(float x)  { return 1.0f / (1.0f + __expf(-x)); }
__device__ __forceinline__ float tanhft(float x){ return 1.0f - 2.0f / (__expf(2.0f * x) + 1.0f); }

__device__ __forceinline__ unsigned int packh(float a, float b) {
    __half2 h = __floats2half2_rn(a, b);
    return reinterpret_cast<unsigned int&>(h);
}

#define MMA_F16(c, A, B0, B1)                                               \
    asm volatile("mma.sync.aligned.m16n8k16.row.col.f32.f16.f16.f32 "       \
                 "{%0,%1,%2,%3}, {%4,%5,%6,%7}, {%8,%9}, {%0,%1,%2,%3};"    \
                 : "+f"(c[0]), "+f"(c[1]), "+f"(c[2]), "+f"(c[3])           \
                 : "r"(A.x), "r"(A.y), "r"(A.z), "r"(A.w), "r"(B0), "r"(B1))

__global__ __launch_bounds__(NTHREADS, 2)
void lstm_mma_kernel(
    const float* __restrict__ seq,  const float* __restrict__ W_ih,
    const float* __restrict__ W_hh, const float* __restrict__ b_ih,
    const float* __restrict__ b_hh, const float* __restrict__ fc1w,
    const float* __restrict__ fc1b, const float* __restrict__ fc2w,
    const float* __restrict__ fc2b, float* __restrict__ out)
{
    extern __shared__ unsigned char wsm[];                 // 32KB W fragments
    __shared__ __align__(16) float stage[8][16][8];        // per-warp h tile (fp32)
    __shared__ __align__(16) float4 sm_wih[8], sm_bias[8];
    __shared__ __align__(16) float hs[2][HID];             // fc1 input rows
    __shared__ __align__(16) float sm_hid[2][HALF];        // fc1 output rows

    const int tid  = threadIdx.x;
    const int cta  = blockIdx.x;
    const int gid  = cta * NTHREADS + tid;
    const int lane = tid & 31;
    const int wti  = tid >> 5;
    const int gq   = lane >> 2;
    const int tg   = lane & 3;

    // ---- prep: W fp16 fragments (gate-interleave reorder). col n:
    // w16=n&15, gate=((w16>>3)<<1)|(w16&1), unit=(n>>4)*4+((w16&7)>>1)
    for (int it = gid; it < 256 * 32 * 32; it += GSZ) {
        int ln  = it & 31;
        int k16 = (it >> 5) & 31;
        int n8  = it >> 10;
        int n   = n8 * 8 + (ln >> 2);
        int w16 = n & 15;
        int gate = ((w16 >> 3) << 1) | (w16 & 1);
        int unit = (n >> 4) * 4 + ((w16 & 7) >> 1);
        const float* wr = W_hh + (gate * HID + unit) * HID + k16 * 16 + ((ln & 3) << 1);
        float2 p0 = *(const float2*)wr;          // k, k+1
        float2 p1 = *(const float2*)(wr + 8);    // k+8, k+9
        uint2 v;
        v.x = packh(p0.x, p0.y);
        v.y = packh(p1.x, p1.y);
        *(uint2*)(g_Wfrag + (((n8 << 5) + k16) << 8) + ln * 8) = v;
    }
    {   // zero h fragments buffer 0 (h = 0)
        uint4 z = make_uint4(0, 0, 0, 0);
        uint4* hz = (uint4*)g_hfrag[0];
        for (int e = gid; e < (1 << 15); e += GSZ) hz[e] = z;
    }
    gridbar0();

    // ---- per-CTA geometry (cross-group co-residency: bids b and b+148 share an
    // SM; 148%4==0, so mixing in (cta>>7) makes co-resident partners belong to
    // DIFFERENT groups -> one CTA's barrier wait overlaps partner's mainloop) ----
    const int grp   = ((cta & 3) + (cta >> 7)) & 3;              // batch band 0..3
    const int tileN = ((cta >> 2) & 31) | ((cta >> 7) << 5);     // 0..63
    const int m16g  = grp * 8 + wti;

    // copy this CTA's W fragments to smem (once; chunks (kt*4+j), 256B each)
    {
        uint4* s4 = (uint4*)wsm;
        const uint4* g4 = (const uint4*)g_Wfrag;
        for (int e = tid; e < WSMEM_BYTES / 16; e += NTHREADS) {
            int w = e & 15, c = e >> 4;
            int kt = c >> 2, j = c & 3;
            s4[e] = __ldcg(&g4[((((tileN * 4 + j) << 5) + kt) << 4) + w]);
        }
    }
    for (int e = tid; e < 32; e += NTHREADS) {
        int u = e >> 2, g = e & 3;
        int ku = tileN * 8 + u;
        ((float*)sm_wih)[e]  = W_ih[g * HID + ku];
        ((float*)sm_bias)[e] = b_ih[g * HID + ku] + b_hh[g * HID + ku];
    }
    __syncthreads();

    float creg[2][2];                      // [rh][block b]
    creg[0][0] = creg[0][1] = creg[1][0] = creg[1][1] = 0.0f;

    const int row_base = grp * 128 + wti * 16 + gq;
    const int k16w  = tileN >> 1;          // A-fragment k16 this CTA co-writes
    const int khalf = tileN & 1;           // which 8-byte half of each lane slot
    const int c0    = k16w;                // rotated k-loop start (de-convoy L2)
    unsigned int* mycnt = &g_cnt[grp][tileN][0];

    // ---- recurrent loop ----
    for (int t = 0; t < TLEN; ++t) {
        const unsigned char* hin  = g_hfrag[t & 1];
        unsigned char*       hout = g_hfrag[(t + 1) & 1];
        const unsigned char* abase = hin + ((size_t)(m16g * 32) << 9) + lane * 16;
        const unsigned char* wbase = wsm + lane * 8;

        // xv loads: L1 stays warm (no fences/IVALL in this scheme)
        float xv0 = seq[row_base * TLEN + t];
        float xv1 = seq[(row_base + 8) * TLEN + t];

        float acc[4][4];
        #pragma unroll
        for (int j = 0; j < 4; ++j)
            #pragma unroll
            for (int c = 0; c < 4; ++c) acc[j][c] = 0.0f;

        uint4 ah[2];                       // __ldcg: L2-coherent A fragments
        ah[0] = __ldcg((const uint4*)(abase + ((size_t)c0 << 9)));
        ah[1] = __ldcg((const uint4*)(abase + ((size_t)((c0 + 1) & 31) << 9)));

        #pragma unroll 2
        for (int kt = 0; kt < 32; ++kt) {
            const int s = kt & 1;
            const int c = (c0 + kt) & 31;
            uint2 bw[4];
            #pragma unroll
            for (int j = 0; j < 4; ++j)
                bw[j] = *(const uint2*)(wbase + (((c << 2) + j) << 8));
            #pragma unroll
            for (int j = 0; j < 4; ++j) MMA_F16(acc[j], ah[s], bw[j].x, bw[j].y);
            if (kt + 2 < 32)
                ah[s] = __ldcg((const uint4*)(abase + ((size_t)((c0 + kt + 2) & 31) << 9)));
        }

        // ---- epilogue: gates -> c,h ; stage h (fp32) ----
        #pragma unroll
        for (int rh = 0; rh < 2; ++rh) {
            float xv = rh ? xv1 : xv0;
            #pragma unroll
            for (int b = 0; b < 2; ++b) {
                float4 wv = sm_wih[b * 4 + tg];
                float4 bv = sm_bias[b * 4 + tg];
                float gi = acc[2*b  ][rh*2+0] + xv * wv.x + bv.x;
                float gf = acc[2*b  ][rh*2+1] + xv * wv.y + bv.y;
                float gg = acc[2*b+1][rh*2+0] + xv * wv.z + bv.z;
                float go = acc[2*b+1][rh*2+1] + xv * wv.w + bv.w;
                float cc = sigf(gf) * creg[rh][b] + sigf(gi) * tanhft(gg);
                creg[rh][b] = cc;
                float hv = sigf(go) * tanhft(cc);
                stage[wti][gq + rh * 8][b * 4 + tg] = hv;
                if (t == TLEN - 1)
                    g_hfin[(row_base + rh * 8) * HID + tileN * 8 + b * 4 + tg] = hv;
            }
        }
        __syncwarp();
        // repack: this CTA supplies k-half 'khalf' of A fragment (m16g, k16w)
        {
            float a0 = stage[wti][gq    ][tg * 2];
            float a1 = stage[wti][gq    ][tg * 2 + 1];
            float b0 = stage[wti][gq + 8][tg * 2];
            float b1 = stage[wti][gq + 8][tg * 2 + 1];
            unsigned int r0 = packh(a0, a1), r1 = packh(b0, b1);
            unsigned char* op = hout + ((size_t)(m16g * 32 + k16w) << 9)
                                     + lane * 16 + khalf * 8;
            *(uint2*)op = make_uint2(r0, r1);
        }
        // per-thread release arrival: pairs with consumers' ld.acquire (no fences)
        red_release_add1(mycnt);

        // wait: all 64 producers of this group at epoch t+1 (256 arrivals each)
        if (wti == 0) {
            const unsigned int tgt = 256u * (unsigned int)(t + 1);
            const unsigned int* p0 = &g_cnt[grp][lane][0];
            const unsigned int* p1 = &g_cnt[grp][lane + 32][0];
            while (__any_sync(0xffffffffu,
                   (ld_acquire(p0) < tgt) || (ld_acquire(p1) < tgt))) { }
        }
        __syncthreads();
    }

    // ---- full sync; reset counters for next graph replay ----
    gridbar0();
    if (tid == 0)
        *(volatile unsigned int*)mycnt = 0u;

    // ---- fc1: hid = relu(h @ fc1w^T + fc1b), 2 batch rows per CTA ----
    const int bb = grp * 128 + tileN * 2;
    {
        for (int e = tid; e < 2 * HID; e += NTHREADS)
            hs[e >> 9][e & 511] = g_hfin[(bb + (e >> 9)) * HID + (e & 511)];
        __syncthreads();
        int n = tid;                            // HALF == 256 == NTHREADS
        const float* wr = fc1w + n * HID;
        float s0 = fc1b[n], s1 = s0;
        #pragma unroll 8
        for (int k = 0; k < HID; ++k) {
            float w = wr[k];
            s0 += hs[0][k] * w; s1 += hs[1][k] * w;
        }
        sm_hid[0][n] = fmaxf(s0, 0.0f);
        sm_hid[1][n] = fmaxf(s1, 0.0f);
    }
    __syncthreads();

    // ---- fc2 (rows bb, bb+1) ----
    for (int i = tid; i < 2 * TGT; i += NTHREADS) {
        int r  = i / TGT;
        int tt = i - r * TGT;
        const float* hr = sm_hid[r];
        const float* wr = fc2w + tt * HALF;
        float s = fc2b[tt];
        #pragma unroll 8
        for (int k = 0; k < HALF; ++k) s += hr[k] * wr[k];
        out[(bb + r) * TGT + tt] = s;
    }
}

extern "C" void kernel_launch(void* const* d_in, const int* in_sizes, int n_in,
                              void* d_out, int out_size) {
    (void)in_sizes; (void)n_in; (void)out_size;
    cudaFuncSetAttribute(lstm_mma_kernel,
                         cudaFuncAttributeMaxDynamicSharedMemorySize, WSMEM_BYTES);
    lstm_mma_kernel<<<NCTAS, NTHREADS, WSMEM_BYTES>>>(
        (const float*)d_in[0], (const float*)d_in[1], (const float*)d_in[2],
        (const float*)d_in[3], (const float*)d_in[4], (const float*)d_in[5],
        (const float*)d_in[6], (const float*)d_in[7], (const float*)d_in[8],
        (float*)d_out);
}

// round 16
// speedup vs baseline: 1.9768x; 1.1258x over previous
#include <cuda_runtime.h>
#include <cuda_fp16.h>

#define BATCH 512
#define TLEN  256
#define HID   512
#define HALF  256
#define TGT   28

#define NTHREADS 256
#define NCTAS 256
#define GSZ (NCTAS * NTHREADS)
#define WSMEM_BYTES 32768   // 32 k16 x 2 j2 x 512B (paired-n8 fp16 W fragments)

// ---------------- device scratch ----------------
// A(h) fragment per (m16,k16): 512B = lane*16 (4 .f16x2 regs)
__device__ __align__(16) unsigned char g_hfrag[2][1 << 19];
// B(W) fragment per (n8,k16): 256B = lane*8 : {b0, b1} fp16x2
__device__ __align__(16) unsigned char g_Wfrag[2 << 20];
__device__ __align__(16) float g_hfin[BATCH * HID];
__device__ unsigned int g_barcnt0;
__device__ volatile unsigned int g_bargen0;
// arrival counters, one per (group, producer CTA), 128B apart (L2-atom friendly)
__device__ unsigned int g_cnt[4][64][32];

// full-grid barrier (sense-reversing; replay-safe; prep/tail only)
__device__ __forceinline__ void gridbar0() {
    __threadfence();
    __syncthreads();
    if (threadIdx.x == 0) {
        unsigned int gen = g_bargen0;
        if (atomicAdd(&g_barcnt0, 1u) == NCTAS - 1u) {
            g_barcnt0 = 0u;
            __threadfence();
            g_bargen0 = gen + 1u;
        } else {
            while (g_bargen0 == gen) { }
            __threadfence();
        }
    }
    __syncthreads();
}

__device__ __forceinline__ unsigned int ld_acquire(const unsigned int* p) {
    unsigned int v;
    asm volatile("ld.acquire.gpu.global.b32 %0, [%1];" : "=r"(v) : "l"(p) : "memory");
    return v;
}
__device__ __forceinline__ void red_release_add1(unsigned int* p) {
    asm volatile("red.release.gpu.global.add.u32 [%0], %1;" :: "l"(p), "r"(1u) : "memory");
}

__device__ __forceinline__ float sigf(float x)  { return 1.0f / (1.0f + __expf(-x)); }
__device__ __forceinline__ float tanhft(float x){ return 1.0f - 2.0f / (__expf(2.0f * x) + 1.0f); }

__device__ __forceinline__ unsigned int packh(float a, float b) {
    __half2 h = __floats2half2_rn(a, b);
    return reinterpret_cast<unsigned int&>(h);
}

#define MMA_F16(c, A, B0, B1)                                               \
    asm volatile("mma.sync.aligned.m16n8k16.row.col.f32.f16.f16.f32 "       \
                 "{%0,%1,%2,%3}, {%4,%5,%6,%7}, {%8,%9}, {%0,%1,%2,%3};"    \
                 : "+f"(c[0]), "+f"(c[1]), "+f"(c[2]), "+f"(c[3])           \
                 : "r"(A.x), "r"(A.y), "r"(A.z), "r"(A.w), "r"(B0), "r"(B1))

__global__ __launch_bounds__(NTHREADS, 2)
void lstm_mma_kernel(
    const float* __restrict__ seq,  const float* __restrict__ W_ih,
    const float* __restrict__ W_hh, const float* __restrict__ b_ih,
    const float* __restrict__ b_hh, const float* __restrict__ fc1w,
    const float* __restrict__ fc1b, const float* __restrict__ fc2w,
    const float* __restrict__ fc2b, float* __restrict__ out)
{
    extern __shared__ unsigned char wsm[];                 // 32KB W fragments
    __shared__ __align__(16) float stage[8][16][8];        // per-warp h tile (fp32)
    __shared__ __align__(16) float4 sm_wih[8], sm_bias[8];
    __shared__ __align__(16) float hs[2][HID];             // fc1 input rows
    __shared__ __align__(16) float sm_hid[2][HALF];        // fc1 output rows

    const int tid  = threadIdx.x;
    const int cta  = blockIdx.x;
    const int gid  = cta * NTHREADS + tid;
    const int lane = tid & 31;
    const int wti  = tid >> 5;
    const int gq   = lane >> 2;
    const int tg   = lane & 3;

    // ---- prep: W fp16 fragments (gate-interleave reorder). col n:
    // w16=n&15, gate=((w16>>3)<<1)|(w16&1), unit=(n>>4)*4+((w16&7)>>1)
    for (int it = gid; it < 256 * 32 * 32; it += GSZ) {
        int ln  = it & 31;
        int k16 = (it >> 5) & 31;
        int n8  = it >> 10;
        int n   = n8 * 8 + (ln >> 2);
        int w16 = n & 15;
        int gate = ((w16 >> 3) << 1) | (w16 & 1);
        int unit = (n >> 4) * 4 + ((w16 & 7) >> 1);
        const float* wr = W_hh + (gate * HID + unit) * HID + k16 * 16 + ((ln & 3) << 1);
        float2 p0 = *(const float2*)wr;          // k, k+1
        float2 p1 = *(const float2*)(wr + 8);    // k+8, k+9
        uint2 v;
        v.x = packh(p0.x, p0.y);
        v.y = packh(p1.x, p1.y);
        *(uint2*)(g_Wfrag + (((n8 << 5) + k16) << 8) + ln * 8) = v;
    }
    {   // zero h fragments buffer 0 (h = 0)
        uint4 z = make_uint4(0, 0, 0, 0);
        uint4* hz = (uint4*)g_hfrag[0];
        for (int e = gid; e < (1 << 15); e += GSZ) hz[e] = z;
    }
    gridbar0();

    // ---- per-CTA geometry (cross-group co-residency: bids b and b+148 share an
    // SM; 148%4==0, so mixing in (cta>>7) makes co-resident partners belong to
    // DIFFERENT groups -> one CTA's barrier wait overlaps partner's mainloop) ----
    const int grp   = ((cta & 3) + (cta >> 7)) & 3;              // batch band 0..3
    const int tileN = ((cta >> 2) & 31) | ((cta >> 7) << 5);     // 0..63
    const int m16g  = grp * 8 + wti;

    // copy this CTA's W fragments to smem, paired-n8 layout:
    // chunk (k16*2 + j2) of 512B; lane slot 16B = {frag(2j2)[lane], frag(2j2+1)[lane]}
    {
        uint4* s4 = (uint4*)wsm;
        for (int e = tid; e < WSMEM_BYTES / 16; e += NTHREADS) {
            int w = e & 31, c = e >> 5;
            int kt = c >> 1, j2 = c & 1;
            const unsigned char* f0 =
                g_Wfrag + ((((tileN * 4 + 2 * j2)     << 5) + kt) << 8) + w * 8;
            const unsigned char* f1 =
                g_Wfrag + ((((tileN * 4 + 2 * j2 + 1) << 5) + kt) << 8) + w * 8;
            uint2 lo = __ldcg((const uint2*)f0);
            uint2 hi = __ldcg((const uint2*)f1);
            s4[e] = make_uint4(lo.x, lo.y, hi.x, hi.y);
        }
    }
    for (int e = tid; e < 32; e += NTHREADS) {
        int u = e >> 2, g = e & 3;
        int ku = tileN * 8 + u;
        ((float*)sm_wih)[e]  = W_ih[g * HID + ku];
        ((float*)sm_bias)[e] = b_ih[g * HID + ku] + b_hh[g * HID + ku];
    }
    __syncthreads();

    float creg[2][2];                      // [rh][block b]
    creg[0][0] = creg[0][1] = creg[1][0] = creg[1][1] = 0.0f;

    const int row_base = grp * 128 + wti * 16 + gq;
    const int k16w  = tileN >> 1;          // A-fragment k16 this CTA co-writes
    const int khalf = tileN & 1;           // which 8-byte half of each lane slot
    const int c0    = k16w;                // rotated k-loop start (de-convoy L2)
    unsigned int* mycnt = &g_cnt[grp][tileN][0];

    // ---- recurrent loop ----
    for (int t = 0; t < TLEN; ++t) {
        const unsigned char* hin  = g_hfrag[t & 1];
        unsigned char*       hout = g_hfrag[(t + 1) & 1];
        const unsigned char* abase = hin + ((size_t)(m16g * 32) << 9) + lane * 16;
        const unsigned char* wbase = wsm + lane * 16;

        // xv loads: L1 stays warm (no fences/IVALL in this scheme)
        float xv0 = seq[row_base * TLEN + t];
        float xv1 = seq[(row_base + 8) * TLEN + t];

        float acc[4][4];
        #pragma unroll
        for (int j = 0; j < 4; ++j)
            #pragma unroll
            for (int c = 0; c < 4; ++c) acc[j][c] = 0.0f;

        uint4 ah[4];                       // depth-4 A prefetch (__ldcg, L2-coherent)
        #pragma unroll
        for (int p = 0; p < 4; ++p)
            ah[p] = __ldcg((const uint4*)(abase + ((size_t)((c0 + p) & 31) << 9)));

        #pragma unroll 4
        for (int kt = 0; kt < 32; ++kt) {
            const int s = kt & 3;
            const int c = (c0 + kt) & 31;
            uint4 b4[2];
            #pragma unroll
            for (int j2 = 0; j2 < 2; ++j2)
                b4[j2] = *(const uint4*)(wbase + (((c << 1) + j2) << 9));
            #pragma unroll
            for (int j2 = 0; j2 < 2; ++j2) {
                MMA_F16(acc[2*j2    ], ah[s], b4[j2].x, b4[j2].y);
                MMA_F16(acc[2*j2 + 1], ah[s], b4[j2].z, b4[j2].w);
            }
            if (kt + 4 < 32)
                ah[s] = __ldcg((const uint4*)(abase + ((size_t)((c0 + kt + 4) & 31) << 9)));
        }

        // ---- epilogue: gates -> c,h ; stage h (fp32) ----
        #pragma unroll
        for (int rh = 0; rh < 2; ++rh) {
            float xv = rh ? xv1 : xv0;
            #pragma unroll
            for (int b = 0; b < 2; ++b) {
                float4 wv = sm_wih[b * 4 + tg];
                float4 bv = sm_bias[b * 4 + tg];
                float gi = acc[2*b  ][rh*2+0] + xv * wv.x + bv.x;
                float gf = acc[2*b  ][rh*2+1] + xv * wv.y + bv.y;
                float gg = acc[2*b+1][rh*2+0] + xv * wv.z + bv.z;
                float go = acc[2*b+1][rh*2+1] + xv * wv.w + bv.w;
                float cc = sigf(gf) * creg[rh][b] + sigf(gi) * tanhft(gg);
                creg[rh][b] = cc;
                float hv = sigf(go) * tanhft(cc);
                stage[wti][gq + rh * 8][b * 4 + tg] = hv;
                if (t == TLEN - 1)
                    g_hfin[(row_base + rh * 8) * HID + tileN * 8 + b * 4 + tg] = hv;
            }
        }
        __syncwarp();
        // repack: this CTA supplies k-half 'khalf' of A fragment (m16g, k16w)
        {
            float a0 = stage[wti][gq    ][tg * 2];
            float a1 = stage[wti][gq    ][tg * 2 + 1];
            float b0 = stage[wti][gq + 8][tg * 2];
            float b1 = stage[wti][gq + 8][tg * 2 + 1];
            unsigned int r0 = packh(a0, a1), r1 = packh(b0, b1);
            unsigned char* op = hout + ((size_t)(m16g * 32 + k16w) << 9)
                                     + lane * 16 + khalf * 8;
            *(uint2*)op = make_uint2(r0, r1);
        }
        // per-thread release arrival: pairs with consumers' ld.acquire (no fences)
        red_release_add1(mycnt);

        // wait: warps 0 and 1 split the 64 counters (32 each, one acquire/lane)
        if (wti < 2) {
            const unsigned int tgt = 256u * (unsigned int)(t + 1);
            const unsigned int* p = &g_cnt[grp][wti * 32 + lane][0];
            while (__any_sync(0xffffffffu, ld_acquire(p) < tgt)) { }
        }
        __syncthreads();
    }

    // ---- full sync; reset counters for next graph replay ----
    gridbar0();
    if (tid == 0)
        *(volatile unsigned int*)mycnt = 0u;

    // ---- fc1: hid = relu(h @ fc1w^T + fc1b), 2 batch rows per CTA ----
    const int bb = grp * 128 + tileN * 2;
    {
        for (int e = tid; e < 2 * HID; e += NTHREADS)
            hs[e >> 9][e & 511] = g_hfin[(bb + (e >> 9)) * HID + (e & 511)];
        __syncthreads();
        int n = tid;                            // HALF == 256 == NTHREADS
        const float* wr = fc1w + n * HID;
        float s0 = fc1b[n], s1 = s0;
        #pragma unroll 8
        for (int k = 0; k < HID; ++k) {
            float w = wr[k];
            s0 += hs[0][k] * w; s1 += hs[1][k] * w;
        }
        sm_hid[0][n] = fmaxf(s0, 0.0f);
        sm_hid[1][n] = fmaxf(s1, 0.0f);
    }
    __syncthreads();

    // ---- fc2 (rows bb, bb+1) ----
    for (int i = tid; i < 2 * TGT; i += NTHREADS) {
        int r  = i / TGT;
        int tt = i - r * TGT;
        const float* hr = sm_hid[r];
        const float* wr = fc2w + tt * HALF;
        float s = fc2b[tt];
        #pragma unroll 8
        for (int k = 0; k < HALF; ++k) s += hr[k] * wr[k];
        out[(bb + r) * TGT + tt] = s;
    }
}

extern "C" void kernel_launch(void* const* d_in, const int* in_sizes, int n_in,
                              void* d_out, int out_size) {
    (void)in_sizes; (void)n_in; (void)out_size;
    cudaFuncSetAttribute(lstm_mma_kernel,
                         cudaFuncAttributeMaxDynamicSharedMemorySize, WSMEM_BYTES);
    lstm_mma_kernel<<<NCTAS, NTHREADS, WSMEM_BYTES>>>(
        (const float*)d_in[0], (const float*)d_in[1], (const float*)d_in[2],
        (const float*)d_in[3], (const float*)d_in[4], (const float*)d_in[5],
        (const float*)d_in[6], (const float*)d_in[7], (const float*)d_in[8],
        (float*)d_out);
}

// round 17
// speedup vs baseline: 1.9881x; 1.0057x over previous
#include <cuda_runtime.h>
#include <cuda_fp16.h>

#define BATCH 512
#define TLEN  256
#define HID   512
#define HALF  256
#define TGT   28

#define NTHREADS 256
#define NCTAS 256
#define GSZ (NCTAS * NTHREADS)
#define WSMEM_BYTES 32768   // 32 kpos x 2 j2 x 512B (paired-n8 fp16 W fragments)

// ---------------- device scratch ----------------
// A(h) fragment per (m16,k16): 512B = lane*16 (4 .f16x2 regs)
__device__ __align__(16) unsigned char g_hfrag[2][1 << 19];
// B(W) fragment per (n8,k16): 256B = lane*8 : {b0, b1} fp16x2
__device__ __align__(16) unsigned char g_Wfrag[2 << 20];
__device__ __align__(16) float g_hfin[BATCH * HID];
__device__ unsigned int g_barcnt0;
__device__ volatile unsigned int g_bargen0;
// arrival counters, one per (group, producer CTA), 128B apart (L2-atom friendly)
__device__ unsigned int g_cnt[4][64][32];

// full-grid barrier (sense-reversing; replay-safe; prep/tail only)
__device__ __forceinline__ void gridbar0() {
    __threadfence();
    __syncthreads();
    if (threadIdx.x == 0) {
        unsigned int gen = g_bargen0;
        if (atomicAdd(&g_barcnt0, 1u) == NCTAS - 1u) {
            g_barcnt0 = 0u;
            __threadfence();
            g_bargen0 = gen + 1u;
        } else {
            while (g_bargen0 == gen) { }
            __threadfence();
        }
    }
    __syncthreads();
}

__device__ __forceinline__ unsigned int ld_acquire(const unsigned int* p) {
    unsigned int v;
    asm volatile("ld.acquire.gpu.global.b32 %0, [%1];" : "=r"(v) : "l"(p) : "memory");
    return v;
}
__device__ __forceinline__ void red_release_add1(unsigned int* p) {
    asm volatile("red.release.gpu.global.add.u32 [%0], %1;" :: "l"(p), "r"(1u) : "memory");
}

__device__ __forceinline__ float sigf(float x)  { return 1.0f / (1.0f + __expf(-x)); }
__device__ __forceinline__ float tanhft(float x){ return 1.0f - 2.0f / (__expf(2.0f * x) + 1.0f); }

__device__ __forceinline__ unsigned int packh(float a, float b) {
    __half2 h = __floats2half2_rn(a, b);
    return reinterpret_cast<unsigned int&>(h);
}

#define MMA_F16(c, A, B0, B1)                                               \
    asm volatile("mma.sync.aligned.m16n8k16.row.col.f32.f16.f16.f32 "       \
                 "{%0,%1,%2,%3}, {%4,%5,%6,%7}, {%8,%9}, {%0,%1,%2,%3};"    \
                 : "+f"(c[0]), "+f"(c[1]), "+f"(c[2]), "+f"(c[3])           \
                 : "r"(A.x), "r"(A.y), "r"(A.z), "r"(A.w), "r"(B0), "r"(B1))

__global__ __launch_bounds__(NTHREADS, 2)
void lstm_mma_kernel(
    const float* __restrict__ seq,  const float* __restrict__ W_ih,
    const float* __restrict__ W_hh, const float* __restrict__ b_ih,
    const float* __restrict__ b_hh, const float* __restrict__ fc1w,
    const float* __restrict__ fc1b, const float* __restrict__ fc2w,
    const float* __restrict__ fc2b, float* __restrict__ out)
{
    extern __shared__ unsigned char wsm[];                 // 32KB W fragments
    __shared__ __align__(16) float stage[8][16][8];        // per-warp h tile (fp32)
    __shared__ __align__(16) float4 sm_wih[8], sm_bias[8];
    __shared__ __align__(16) float hs[2][HID];             // fc1 input rows
    __shared__ __align__(16) float sm_hid[2][HALF];        // fc1 output rows

    const int tid  = threadIdx.x;
    const int cta  = blockIdx.x;
    const int gid  = cta * NTHREADS + tid;
    const int lane = tid & 31;
    const int wti  = tid >> 5;
    const int gq   = lane >> 2;
    const int tg   = lane & 3;

    // ---- prep: W fp16 fragments (gate-interleave reorder). col n:
    // w16=n&15, gate=((w16>>3)<<1)|(w16&1), unit=(n>>4)*4+((w16&7)>>1)
    for (int it = gid; it < 256 * 32 * 32; it += GSZ) {
        int ln  = it & 31;
        int k16 = (it >> 5) & 31;
        int n8  = it >> 10;
        int n   = n8 * 8 + (ln >> 2);
        int w16 = n & 15;
        int gate = ((w16 >> 3) << 1) | (w16 & 1);
        int unit = (n >> 4) * 4 + ((w16 & 7) >> 1);
        const float* wr = W_hh + (gate * HID + unit) * HID + k16 * 16 + ((ln & 3) << 1);
        float2 p0 = *(const float2*)wr;          // k, k+1
        float2 p1 = *(const float2*)(wr + 8);    // k+8, k+9
        uint2 v;
        v.x = packh(p0.x, p0.y);
        v.y = packh(p1.x, p1.y);
        *(uint2*)(g_Wfrag + (((n8 << 5) + k16) << 8) + ln * 8) = v;
    }
    {   // zero h fragments buffer 0 (h = 0)
        uint4 z = make_uint4(0, 0, 0, 0);
        uint4* hz = (uint4*)g_hfrag[0];
        for (int e = gid; e < (1 << 15); e += GSZ) hz[e] = z;
    }
    gridbar0();

    // ---- per-CTA geometry (cross-group co-residency: bids b and b+148 share an
    // SM; 148%4==0, so mixing in (cta>>7) makes co-resident partners belong to
    // DIFFERENT groups -> one CTA's barrier wait overlaps partner's mainloop) ----
    const int grp   = ((cta & 3) + (cta >> 7)) & 3;              // batch band 0..3
    const int tileN = ((cta >> 2) & 31) | ((cta >> 7) << 5);     // 0..63
    const int m16g  = grp * 8 + wti;
    const int k16w  = tileN >> 1;          // A-fragment k16 this CTA co-writes
    const int khalf = tileN & 1;           // which 8-byte half of each lane slot
    const int c0    = k16w;                // rotated k order (de-convoy L2 on A)

    // copy this CTA's W fragments to smem, paired-n8 layout, PRE-ROTATED:
    // smem position p holds k-chunk (c0+p)&31  ->  mainloop LDS offsets are
    // sequential (compile-time immediates under full unroll)
    {
        uint4* s4 = (uint4*)wsm;
        for (int e = tid; e < WSMEM_BYTES / 16; e += NTHREADS) {
            int w = e & 31, c = e >> 5;
            int kpos = c >> 1, j2 = c & 1;
            int ksrc = (c0 + kpos) & 31;
            const unsigned char* f0 =
                g_Wfrag + ((((tileN * 4 + 2 * j2)     << 5) + ksrc) << 8) + w * 8;
            const unsigned char* f1 =
                g_Wfrag + ((((tileN * 4 + 2 * j2 + 1) << 5) + ksrc) << 8) + w * 8;
            uint2 lo = __ldcg((const uint2*)f0);
            uint2 hi = __ldcg((const uint2*)f1);
            s4[e] = make_uint4(lo.x, lo.y, hi.x, hi.y);
        }
    }
    for (int e = tid; e < 32; e += NTHREADS) {
        int u = e >> 2, g = e & 3;
        int ku = tileN * 8 + u;
        ((float*)sm_wih)[e]  = W_ih[g * HID + ku];
        ((float*)sm_bias)[e] = b_ih[g * HID + ku] + b_hh[g * HID + ku];
    }
    __syncthreads();

    float creg[2][2];                      // [rh][block b]
    creg[0][0] = creg[0][1] = creg[1][0] = creg[1][1] = 0.0f;

    const int row_base = grp * 128 + wti * 16 + gq;
    unsigned int* mycnt = &g_cnt[grp][tileN][0];

    // ---- recurrent loop ----
    for (int t = 0; t < TLEN; ++t) {
        const unsigned char* hin  = g_hfrag[t & 1];
        unsigned char*       hout = g_hfrag[(t + 1) & 1];
        const unsigned char* abase = hin + ((size_t)(m16g * 32) << 9) + lane * 16;
        const unsigned char* wbase = wsm + lane * 16;

        // xv loads: L1 stays warm (no fences/IVALL in this scheme)
        float xv0 = seq[row_base * TLEN + t];
        float xv1 = seq[(row_base + 8) * TLEN + t];

        float acc[4][4];
        #pragma unroll
        for (int j = 0; j < 4; ++j)
            #pragma unroll
            for (int c = 0; c < 4; ++c) acc[j][c] = 0.0f;

        uint4 ah[4];                       // depth-4 A prefetch (__ldcg, L2-coherent)
        #pragma unroll
        for (int p = 0; p < 4; ++p)
            ah[p] = __ldcg((const uint4*)(abase + ((size_t)((c0 + p) & 31) << 9)));

        #pragma unroll
        for (int kt = 0; kt < 32; ++kt) {  // FULL unroll: B offsets immediate
            const int s = kt & 3;
            uint4 b4[2];
            #pragma unroll
            for (int j2 = 0; j2 < 2; ++j2)
                b4[j2] = *(const uint4*)(wbase + (((kt << 1) + j2) << 9));
            #pragma unroll
            for (int j2 = 0; j2 < 2; ++j2) {
                MMA_F16(acc[2*j2    ], ah[s], b4[j2].x, b4[j2].y);
                MMA_F16(acc[2*j2 + 1], ah[s], b4[j2].z, b4[j2].w);
            }
            if (kt + 4 < 32)
                ah[s] = __ldcg((const uint4*)(abase + ((size_t)((c0 + kt + 4) & 31) << 9)));
        }

        // ---- epilogue: gates -> c,h ; stage h (fp32) ----
        #pragma unroll
        for (int rh = 0; rh < 2; ++rh) {
            float xv = rh ? xv1 : xv0;
            #pragma unroll
            for (int b = 0; b < 2; ++b) {
                float4 wv = sm_wih[b * 4 + tg];
                float4 bv = sm_bias[b * 4 + tg];
                float gi = acc[2*b  ][rh*2+0] + xv * wv.x + bv.x;
                float gf = acc[2*b  ][rh*2+1] + xv * wv.y + bv.y;
                float gg = acc[2*b+1][rh*2+0] + xv * wv.z + bv.z;
                float go = acc[2*b+1][rh*2+1] + xv * wv.w + bv.w;
                float cc = sigf(gf) * creg[rh][b] + sigf(gi) * tanhft(gg);
                creg[rh][b] = cc;
                float hv = sigf(go) * tanhft(cc);
                stage[wti][gq + rh * 8][b * 4 + tg] = hv;
                if (t == TLEN - 1)
                    g_hfin[(row_base + rh * 8) * HID + tileN * 8 + b * 4 + tg] = hv;
            }
        }
        __syncwarp();
        // repack: this CTA supplies k-half 'khalf' of A fragment (m16g, k16w)
        {
            float a0 = stage[wti][gq    ][tg * 2];
            float a1 = stage[wti][gq    ][tg * 2 + 1];
            float b0 = stage[wti][gq + 8][tg * 2];
            float b1 = stage[wti][gq + 8][tg * 2 + 1];
            unsigned int r0 = packh(a0, a1), r1 = packh(b0, b1);
            unsigned char* op = hout + ((size_t)(m16g * 32 + k16w) << 9)
                                     + lane * 16 + khalf * 8;
            *(uint2*)op = make_uint2(r0, r1);
        }
        // warp-level release arrival: __syncwarp orders all lanes' repack STGs
        // before lane0's red.release (8 arrivals/CTA/step instead of 256)
        __syncwarp();
        if (lane == 0)
            red_release_add1(mycnt);

        // wait: warps 0 and 1 split the 64 counters (32 each, one acquire/lane)
        if (wti < 2) {
            const unsigned int tgt = 8u * (unsigned int)(t + 1);
            const unsigned int* p = &g_cnt[grp][wti * 32 + lane][0];
            while (__any_sync(0xffffffffu, ld_acquire(p) < tgt)) { }
        }
        __syncthreads();
    }

    // ---- full sync; reset counters for next graph replay ----
    gridbar0();
    if (tid == 0)
        *(volatile unsigned int*)mycnt = 0u;

    // ---- fc1: hid = relu(h @ fc1w^T + fc1b), 2 batch rows per CTA ----
    const int bb = grp * 128 + tileN * 2;
    {
        for (int e = tid; e < 2 * HID; e += NTHREADS)
            hs[e >> 9][e & 511] = g_hfin[(bb + (e >> 9)) * HID + (e & 511)];
        __syncthreads();
        int n = tid;                            // HALF == 256 == NTHREADS
        const float* wr = fc1w + n * HID;
        float s0 = fc1b[n], s1 = s0;
        #pragma unroll 8
        for (int k = 0; k < HID; ++k) {
            float w = wr[k];
            s0 += hs[0][k] * w; s1 += hs[1][k] * w;
        }
        sm_hid[0][n] = fmaxf(s0, 0.0f);
        sm_hid[1][n] = fmaxf(s1, 0.0f);
    }
    __syncthreads();

    // ---- fc2 (rows bb, bb+1) ----
    for (int i = tid; i < 2 * TGT; i += NTHREADS) {
        int r  = i / TGT;
        int tt = i - r * TGT;
        const float* hr = sm_hid[r];
        const float* wr = fc2w + tt * HALF;
        float s = fc2b[tt];
        #pragma unroll 8
        for (int k = 0; k < HALF; ++k) s += hr[k] * wr[k];
        out[(bb + r) * TGT + tt] = s;
    }
}

extern "C" void kernel_launch(void* const* d_in, const int* in_sizes, int n_in,
                              void* d_out, int out_size) {
    (void)in_sizes; (void)n_in; (void)out_size;
    cudaFuncSetAttribute(lstm_mma_kernel,
                         cudaFuncAttributeMaxDynamicSharedMemorySize, WSMEM_BYTES);
    lstm_mma_kernel<<<NCTAS, NTHREADS, WSMEM_BYTES>>>(
        (const float*)d_in[0], (const float*)d_in[1], (const float*)d_in[2],
        (const float*)d_in[3], (const float*)d_in[4], (const float*)d_in[5],
        (const float*)d_in[6], (const float*)d_in[7], (const float*)d_in[8],
        (float*)d_out);
}